// round 17
// baseline (speedup 1.0000x reference)
#include <cuda_runtime.h>
#include <cuda_fp16.h>
#include <mma.h>

using namespace nvcuda;

#define Mv    32768
#define Ev    262144
#define RANKv 5
#define FILTv 32
#define FINv  32
#define NBv   8
#define VEC   256   // FIN * NB

typedef unsigned long long u64;
typedef unsigned int u32;

struct alignas(8) Edge { int c; float w; };

__device__ __half g_T[4][(size_t)Mv * VEC];
__device__ int    g_cnt[Mv];         // zero at module load; re-zeroed by scan phase each replay
__device__ int    g_rowptr[Mv];      // block-local exclusive scans
__device__ int    g_bsum[32];        // per-1024-chunk totals
__device__ int    g_pos[Ev];
__device__ Edge   g_edge[Ev];
__device__ __half g_W[160 * FILTv];  // W fp16, rows = kr*32+f
__device__ int    g_done;            // hist-blocks arrival counter (reset in-kernel)
__device__ int    g_sdone;           // scan-blocks arrival counter (reset in-kernel)

// warp-wide exclusive scan of g_bsum; base offset for chunk j (per-lane j ok)
__device__ __forceinline__ int chunk_base(int l, int j) {
    int own = g_bsum[l];
    int v = own;
#pragma unroll
    for (int off = 1; off < 32; off <<= 1) {
        int u = __shfl_up_sync(0xffffffffu, v, off);
        if (l >= off) v += u;
    }
    int excl = v - own;
    return __shfl_sync(0xffffffffu, excl, j & 31);
}

// row [start,end) bounds for row m, lane l (full-warp collective)
__device__ __forceinline__ void row_bounds(int m, int l, int& s, int& e) {
    int own = g_bsum[l];
    int v = own;
#pragma unroll
    for (int off = 1; off < 32; off <<= 1) {
        int u = __shfl_up_sync(0xffffffffu, v, off);
        if (l >= off) v += u;
    }
    int excl = v - own;
    s = __shfl_sync(0xffffffffu, excl, m >> 10) + g_rowptr[m];
    e = (m == Mv - 1) ? Ev
        : __shfl_sync(0xffffffffu, excl, ((m + 1) >> 10) & 31) + g_rowptr[m + 1];
}

// ---------------- fused CSR-build front end ----------------
// blocks [0,1024): histogram (+arrive); [1024,5120): x->T0 transpose;
// [5120,5152): spin-then-scan 1024-chunk of g_cnt (+re-zero); 5152: W fp16 convert.
__global__ void __launch_bounds__(256) k_histscan(const int* __restrict__ rows,
                                                  const float* __restrict__ x,
                                                  const float* __restrict__ kern) {
    int t = threadIdx.x, b = blockIdx.x;
    if (b < 1024) {
        int e = b * 256 + t;
        g_pos[e] = atomicAdd(&g_cnt[rows[e]], 1);
        __threadfence();
        __syncthreads();
        if (t == 0) atomicAdd(&g_done, 1);
    } else if (b < 5120) {
        int bb = b - 1024;
        int l = t & 31;
        int m = bb * 8 + (t >> 5);
        int n = l >> 2;
        int f0 = 8 * (l & 3);
        const float* xp = &x[((size_t)n * Mv + m) * FINv + f0];
        float4 va = *(const float4*)xp;
        float4 vb = *(const float4*)(xp + 4);
        uint4 u;
        __half2 h;
        h = __floats2half2_rn(va.x, va.y); u.x = *(u32*)&h;
        h = __floats2half2_rn(va.z, va.w); u.y = *(u32*)&h;
        h = __floats2half2_rn(vb.x, vb.y); u.z = *(u32*)&h;
        h = __floats2half2_rn(vb.z, vb.w); u.w = *(u32*)&h;
        *(uint4*)&g_T[0][(size_t)m * VEC + 8 * l] = u;
    } else if (b < 5152) {
        // wait for all hist blocks
        if (t == 0) {
            while (atomicAdd(&g_done, 0) < 1024) __nanosleep(128);
        }
        __syncthreads();
        __threadfence();
        int chunk = b - 5120;
        int base = chunk * 1024 + t * 4;
        int c0 = g_cnt[base + 0], c1 = g_cnt[base + 1];
        int c2 = g_cnt[base + 2], c3 = g_cnt[base + 3];
        g_cnt[base + 0] = 0; g_cnt[base + 1] = 0;
        g_cnt[base + 2] = 0; g_cnt[base + 3] = 0;
        int s0 = c0, s01 = c0 + c1, s012 = s01 + c2, tot = s012 + c3;
        __shared__ int sh[256];
        sh[t] = tot;
        __syncthreads();
#pragma unroll
        for (int off = 1; off < 256; off <<= 1) {
            int v = (t >= off) ? sh[t - off] : 0;
            __syncthreads();
            sh[t] += v;
            __syncthreads();
        }
        int excl = (t == 0) ? 0 : sh[t - 1];
        g_rowptr[base + 0] = excl;
        g_rowptr[base + 1] = excl + s0;
        g_rowptr[base + 2] = excl + s01;
        g_rowptr[base + 3] = excl + s012;
        if (t == 255) g_bsum[chunk] = sh[255];
        __syncthreads();
        if (t == 0) {
            int d = atomicAdd(&g_sdone, 1);
            if (d == 31) { g_done = 0; g_sdone = 0; }   // restore replay invariant
        }
    } else {
        // W fp32 -> fp16, rows reordered to (kr*32+f)
        for (int i = t; i < 160 * FILTv; i += 256) {
            int row = i >> 5, filt = i & 31;
            int kr = row >> 5, f = row & 31;
            g_W[i] = __float2half_rn(kern[(f * RANKv + kr) * FILTv + filt]);
        }
    }
}

__global__ void __launch_bounds__(256) k_scatter(const int* __restrict__ rows,
                                                 const int* __restrict__ cols,
                                                 const float* __restrict__ vals) {
    int t = threadIdx.x;
    int l = t & 31;
    int e = blockIdx.x * 256 + t;
    int r = rows[e];
    int base = chunk_base(l, r >> 10);
    int idx = base + g_rowptr[r] + g_pos[e];
    Edge ed; ed.c = cols[e] * VEC; ed.w = vals[e];
    g_edge[idx] = ed;
}

// ---- lane-cooperative gather (R13 scalar accumulate: the proven optimum) ----
__device__ __forceinline__ void gather_warp(const __half* __restrict__ Tprev,
                                            int s, int deg, int l,
                                            float2& r0, float2& r1, float2& r2, float2& r3) {
    Edge myEd; myEd.c = 0; myEd.w = 0.f;
    if (l < deg) myEd = g_edge[s + l];       // one coalesced 256B warp load
    int dmain = min(deg, 32);
    int dpad = (dmain + 3) & ~3;             // zero-weight padding to x4

    float a0x=0.f,a0y=0.f,a1x=0.f,a1y=0.f,a2x=0.f,a2y=0.f,a3x=0.f,a3y=0.f;
    for (int i = 0; i < dpad; i += 4) {
        int   c0 = __shfl_sync(0xffffffffu, myEd.c, i + 0);
        float w0 = __shfl_sync(0xffffffffu, myEd.w, i + 0);
        int   c1 = __shfl_sync(0xffffffffu, myEd.c, i + 1);
        float w1 = __shfl_sync(0xffffffffu, myEd.w, i + 1);
        int   c2 = __shfl_sync(0xffffffffu, myEd.c, i + 2);
        float w2 = __shfl_sync(0xffffffffu, myEd.w, i + 2);
        int   c3 = __shfl_sync(0xffffffffu, myEd.c, i + 3);
        float w3 = __shfl_sync(0xffffffffu, myEd.w, i + 3);
        uint4 v0 = *(const uint4*)&Tprev[(size_t)c0 + 8 * l];
        uint4 v1 = *(const uint4*)&Tprev[(size_t)c1 + 8 * l];
        uint4 v2 = *(const uint4*)&Tprev[(size_t)c2 + 8 * l];
        uint4 v3 = *(const uint4*)&Tprev[(size_t)c3 + 8 * l];
#define ACC(V, W) { \
        float2 q0 = __half22float2(*(__half2*)&V.x); \
        float2 q1 = __half22float2(*(__half2*)&V.y); \
        float2 q2 = __half22float2(*(__half2*)&V.z); \
        float2 q3 = __half22float2(*(__half2*)&V.w); \
        a0x += W * q0.x; a0y += W * q0.y; \
        a1x += W * q1.x; a1y += W * q1.y; \
        a2x += W * q2.x; a2y += W * q2.y; \
        a3x += W * q3.x; a3y += W * q3.y; }
        ACC(v0, w0) ACC(v1, w1) ACC(v2, w2) ACC(v3, w3)
#undef ACC
    }
    // fallback for degree > 32 (practically never with E/M = 8)
    for (int i = 32; i < deg; i++) {
        Edge ed = g_edge[s + i];
        uint4 v = *(const uint4*)&Tprev[(size_t)ed.c + 8 * l];
        float wv = ed.w;
        float2 q0 = __half22float2(*(__half2*)&v.x);
        float2 q1 = __half22float2(*(__half2*)&v.y);
        float2 q2 = __half22float2(*(__half2*)&v.z);
        float2 q3 = __half22float2(*(__half2*)&v.w);
        a0x += wv * q0.x; a0y += wv * q0.y;
        a1x += wv * q1.x; a1y += wv * q1.y;
        a2x += wv * q2.x; a2y += wv * q2.y;
        a3x += wv * q3.x; a3y += wv * q3.y;
    }
    r0 = make_float2(a0x, a0y); r1 = make_float2(a1x, a1y);
    r2 = make_float2(a2x, a2y); r3 = make_float2(a3x, a3y);
}

// ---------------- Chebyshev step: one warp per row, fp16 in/out, fp32 accum ----------------
__global__ void __launch_bounds__(256) k_step(int prevIdx, int ppIdx, int curIdx, int isFirst) {
    int t = threadIdx.x;
    int w = t >> 5, l = t & 31;
    int m = blockIdx.x * 8 + w;

    const __half* __restrict__ Tprev = g_T[prevIdx];
    const __half* __restrict__ Tpp   = g_T[ppIdx];
    __half* __restrict__ Tcur        = g_T[curIdx];

    size_t base = (size_t)m * VEC + 8 * l;
    uint4 ppu = make_uint4(0, 0, 0, 0);
    if (!isFirst) ppu = *(const uint4*)&Tpp[base];

    int s, e;
    row_bounds(m, l, s, e);

    float2 a0, a1, a2, a3;
    gather_warp(Tprev, s, e - s, l, a0, a1, a2, a3);

    if (!isFirst) {
        float2 p0 = __half22float2(*(__half2*)&ppu.x);
        float2 p1 = __half22float2(*(__half2*)&ppu.y);
        float2 p2 = __half22float2(*(__half2*)&ppu.z);
        float2 p3 = __half22float2(*(__half2*)&ppu.w);
        a0.x = 2.f * a0.x - p0.x;  a0.y = 2.f * a0.y - p0.y;
        a1.x = 2.f * a1.x - p1.x;  a1.y = 2.f * a1.y - p1.y;
        a2.x = 2.f * a2.x - p2.x;  a2.y = 2.f * a2.y - p2.y;
        a3.x = 2.f * a3.x - p3.x;  a3.y = 2.f * a3.y - p3.y;
    }

    uint4 u;
    __half2 h;
    h = __floats2half2_rn(a0.x, a0.y); u.x = *(u32*)&h;
    h = __floats2half2_rn(a1.x, a1.y); u.y = *(u32*)&h;
    h = __floats2half2_rn(a2.x, a2.y); u.z = *(u32*)&h;
    h = __floats2half2_rn(a3.x, a3.y); u.w = *(u32*)&h;
    *(uint4*)&Tcur[base] = u;
}

// ---------------- fused last step + tensor-core GEMM ----------------
#define A_LD 168   // 160 + 8 halfs pad

__global__ void __launch_bounds__(256) k_step_fin(const float* __restrict__ bias,
                                                  float* __restrict__ out) {
    __shared__ alignas(16) char smBuf[64 * A_LD * 2];     // smA (21504 B) / smC (8192 B) alias
    __shared__ alignas(16) __half smB[160 * FILTv];       // 10240 B
    __shared__ float smBias[16 * FILTv];                  //  2048 B
    __half* smA = (__half*)smBuf;
    float*  smC = (float*)smBuf;

    int t = threadIdx.x;
    int w = t >> 5, l = t & 31;
    int m0 = blockIdx.x * 8;
    int m = m0 + w;
    int n = l >> 2, f0 = 8 * (l & 3);
    int tr = n * 8 + w;

    // stage T0..T3 rows of A
#pragma unroll
    for (int kr = 0; kr < 4; kr++) {
        uint4 v = *(const uint4*)&g_T[kr][(size_t)m * VEC + 8 * l];
        *(uint4*)&smA[tr * A_LD + kr * 32 + f0] = v;
    }

    // B: bulk-copy pre-converted fp16 W; bias rows
    for (int i = t; i < 640; i += 256)
        ((uint4*)smB)[i] = ((const uint4*)g_W)[i];
    for (int i = t; i < 16 * FILTv; i += 256)
        smBias[i] = bias[i & 31];

    // gather T4 = 2 L T3 - T2 for row m
    {
        uint4 ppu = *(const uint4*)&g_T[2][(size_t)m * VEC + 8 * l];
        int s, e;
        row_bounds(m, l, s, e);
        float2 a0, a1, a2, a3;
        gather_warp(g_T[3], s, e - s, l, a0, a1, a2, a3);
        float2 p0 = __half22float2(*(__half2*)&ppu.x);
        float2 p1 = __half22float2(*(__half2*)&ppu.y);
        float2 p2 = __half22float2(*(__half2*)&ppu.z);
        float2 p3 = __half22float2(*(__half2*)&ppu.w);
        uint4 u;
        __half2 h;
        h = __floats2half2_rn(2.f*a0.x - p0.x, 2.f*a0.y - p0.y); u.x = *(u32*)&h;
        h = __floats2half2_rn(2.f*a1.x - p1.x, 2.f*a1.y - p1.y); u.y = *(u32*)&h;
        h = __floats2half2_rn(2.f*a2.x - p2.x, 2.f*a2.y - p2.y); u.z = *(u32*)&h;
        h = __floats2half2_rn(2.f*a3.x - p3.x, 2.f*a3.y - p3.y); u.w = *(u32*)&h;
        *(uint4*)&smA[tr * A_LD + 4 * 32 + f0] = u;
    }
    __syncthreads();

    // wmma: 8 warps -> 8 tiles (row-tile w>>1, col-tile w&1), acc init = bias
    {
        int wr = w >> 1, wc = w & 1;
        wmma::fragment<wmma::accumulator, 16, 16, 16, float> acc;
        wmma::load_matrix_sync(acc, smBias + wc * 16, FILTv, wmma::mem_row_major);
#pragma unroll
        for (int kk = 0; kk < 10; kk++) {
            wmma::fragment<wmma::matrix_a, 16, 16, 16, __half, wmma::row_major> fa;
            wmma::fragment<wmma::matrix_b, 16, 16, 16, __half, wmma::row_major> fb;
            wmma::load_matrix_sync(fa, &smA[16 * wr * A_LD + kk * 16], A_LD);
            wmma::load_matrix_sync(fb, &smB[kk * 16 * FILTv + wc * 16], FILTv);
            wmma::mma_sync(acc, fa, fb, acc);
        }
        __syncthreads();   // all smA reads done before smC overwrites the alias
        wmma::store_matrix_sync(&smC[16 * wr * FILTv + wc * 16], acc, FILTv, wmma::mem_row_major);
    }
    __syncthreads();

    // scatter to out: rows tr = n*8+m_local
    for (int i = t; i < 64 * FILTv; i += 256) {
        int rr = i >> 5, filt = i & 31;
        int nn = rr >> 3, ml = rr & 7;
        out[((size_t)nn * Mv + m0 + ml) * FILTv + filt] = smC[i];
    }
}

extern "C" void kernel_launch(void* const* d_in, const int* in_sizes, int n_in,
                              void* d_out, int out_size) {
    const float* x    = (const float*)d_in[0];
    const float* vals = (const float*)d_in[1];
    const float* kern = (const float*)d_in[2];
    const float* bias = (const float*)d_in[3];
    const int*   rows = (const int*)  d_in[4];
    const int*   cols = (const int*)  d_in[5];
    float* out = (float*)d_out;

    // one-time attribute: prefer max L1 for the zero-smem gather kernels
    static int attr_set = 0;
    if (!attr_set) {
        cudaFuncSetAttribute(k_step, cudaFuncAttributePreferredSharedMemoryCarveout, 0);
        attr_set = 1;
    }

    k_histscan<<<5153, 256>>>(rows, x, kern);         // 1  hist + transpose + scan + W conv
    k_scatter <<<Ev / 256, 256>>>(rows, cols, vals);  // 2
    k_step<<<Mv / 8, 256>>>(0, 0, 1, 1);   // 3  T1 = L T0
    k_step<<<Mv / 8, 256>>>(1, 0, 2, 0);   // 4  T2
    k_step<<<Mv / 8, 256>>>(2, 1, 3, 0);   // 5  T3
    k_step_fin<<<Mv / 8, 256>>>(bias, out);  // 6  T4 + GEMM + out
}